// round 13
// baseline (speedup 1.0000x reference)
#include <cuda_runtime.h>

#define NN 100000
#define NE 1600000
#define HID 128
#define NG 2048
#define FN 16
#define FE 8
#define NB_SCAN 391   /* ceil(NN/256) */

// ---------------- scratch (static device globals; no allocation) -------------
__device__ float g_h [NN * HID];
__device__ float g_hw[NN * HID];
__device__ float g_h2[NN * HID];
__device__ float g_agg8[NN * FE];

__device__ int g_deg [2][NN];
__device__ int g_rp  [2][NN + 1];
__device__ int g_cur [2][NN];
__device__ int g_bsum[2][NB_SCAN];
__device__ int g_boff[2][NB_SCAN];

__device__ int   g_dst_perm[NE];
__device__ float g_val_perm[NE];
__device__ int   g_eid_perm[NE];

__device__ int   g_rpg[NG + 1];
__device__ float g_fp[NG * HID];

// ---------------- helpers ----------------------------------------------------
__device__ __forceinline__ void fma4(float4& a, float s, const float4& w) {
    a.x += s * w.x; a.y += s * w.y; a.z += s * w.z; a.w += s * w.w;
}
__device__ __forceinline__ void relu4(float4& a) {
    a.x = fmaxf(a.x, 0.f); a.y = fmaxf(a.y, 0.f);
    a.z = fmaxf(a.z, 0.f); a.w = fmaxf(a.w, 0.f);
}

// ---------------- zero degree counters ---------------------------------------
__global__ void k_zero() {
    int i = blockIdx.x * blockDim.x + threadIdx.x;
    if (i < NN) { g_deg[0][i] = 0; g_deg[1][i] = 0; }
}

// ---------------- degree histograms ------------------------------------------
__global__ void k_hist(const int* __restrict__ adj_src,
                       const int* __restrict__ e_dst) {
    int i = blockIdx.x * blockDim.x + threadIdx.x;
    int stride = gridDim.x * blockDim.x;
    for (int e = i; e < NE; e += stride) {
        atomicAdd(&g_deg[0][adj_src[e]], 1);
        atomicAdd(&g_deg[1][e_dst[e]], 1);
    }
}

// ---------------- parallel scan: phase 1 (per-block sums) --------------------
__global__ void k_scan_partial(int which) {
    __shared__ int s[256];
    int b = blockIdx.x;
    int i = b * 256 + threadIdx.x;
    int v = (i < NN) ? g_deg[which][i] : 0;
    s[threadIdx.x] = v;
    __syncthreads();
    for (int off = 128; off > 0; off >>= 1) {
        if (threadIdx.x < off) s[threadIdx.x] += s[threadIdx.x + off];
        __syncthreads();
    }
    if (threadIdx.x == 0) g_bsum[which][b] = s[0];
}

// ---------------- parallel scan: phase 2 (scan of block sums, 1 block) -------
__global__ void k_scan_blocks(int which) {
    __shared__ int s[512];
    int tid = threadIdx.x;
    int v = (tid < NB_SCAN) ? g_bsum[which][tid] : 0;
    s[tid] = v;
    __syncthreads();
    for (int off = 1; off < 512; off <<= 1) {
        int t = (tid >= off) ? s[tid - off] : 0;
        __syncthreads();
        s[tid] += t;
        __syncthreads();
    }
    if (tid < NB_SCAN) g_boff[which][tid] = s[tid] - v;   // exclusive
    if (tid == 511) g_rp[which][NN] = s[511];             // total
}

// ---------------- parallel scan: phase 3 (emit rp/cur) ------------------------
__global__ void k_scan_emit(int which) {
    __shared__ int s[256];
    int b = blockIdx.x;
    int tid = threadIdx.x;
    int i = b * 256 + tid;
    int d = (i < NN) ? g_deg[which][i] : 0;
    s[tid] = d;
    __syncthreads();
    for (int off = 1; off < 256; off <<= 1) {
        int t = (tid >= off) ? s[tid - off] : 0;
        __syncthreads();
        s[tid] += t;
        __syncthreads();
    }
    if (i < NN) {
        int rp = g_boff[which][b] + s[tid] - d;
        g_rp[which][i] = rp;
        g_cur[which][i] = rp;
    }
}

// ---------------- CSR fill (permutation) -------------------------------------
__global__ void k_fill(const int* __restrict__ adj_src,
                       const int* __restrict__ adj_dst,
                       const float* __restrict__ adj_val,
                       const int* __restrict__ e_dst) {
    int i = blockIdx.x * blockDim.x + threadIdx.x;
    int stride = gridDim.x * blockDim.x;
    for (int e = i; e < NE; e += stride) {
        int pos = atomicAdd(&g_cur[0][adj_src[e]], 1);
        g_dst_perm[pos] = adj_dst[e];
        g_val_perm[pos] = adj_val[e];
        int p2 = atomicAdd(&g_cur[1][e_dst[e]], 1);
        g_eid_perm[p2] = e;
    }
}

// ---------------- 8-dim raw edge feature aggregation --------------------------
// g_agg8[n][c] = sum over incoming edges e of edge_attr[e][c]
__global__ void k_agg8(const float* __restrict__ edge_attr) {
    int lane = threadIdx.x & 31;
    int wid  = threadIdx.x >> 5;
    int gw = blockIdx.x * (blockDim.x >> 5) + wid;
    int nwarps = gridDim.x * (blockDim.x >> 5);
    int sub = lane >> 3;     // 0..3 : edge slot
    int col = lane & 7;      // 0..7 : feature

    for (int n = gw; n < NN; n += nwarps) {
        int pbeg = g_rp[1][n], pend = g_rp[1][n + 1];
        float v = 0.f;
        for (int p = pbeg + sub; p < pend; p += 4) {
            int e = g_eid_perm[p];
            v += __ldg(edge_attr + (size_t)e * FE + col);
        }
        v += __shfl_down_sync(0xFFFFFFFFu, v, 16);
        v += __shfl_down_sync(0xFFFFFFFFu, v, 8);
        if (lane < 8) g_agg8[(size_t)n * FE + lane] = v;
    }
}

// ---------------- attr embedder: h = relu([node|agg8] @ [Wn;We] + b) ----------
__global__ void k_embed(const float* __restrict__ node_attr,
                        const float* __restrict__ W_node,
                        const float* __restrict__ W_edge,
                        const float* __restrict__ b_embed) {
    __shared__ float sWn[FN * HID];
    __shared__ float sWe[FE * HID];
    for (int i = threadIdx.x; i < FN * HID; i += blockDim.x) sWn[i] = W_node[i];
    for (int i = threadIdx.x; i < FE * HID; i += blockDim.x) sWe[i] = W_edge[i];
    __syncthreads();

    int lane = threadIdx.x & 31;
    int wid  = threadIdx.x >> 5;
    int gw = blockIdx.x * (blockDim.x >> 5) + wid;
    int nwarps = gridDim.x * (blockDim.x >> 5);
    int c0 = lane * 4;

    for (int n = gw; n < NN; n += nwarps) {
        float4 acc = *reinterpret_cast<const float4*>(b_embed + c0);
        const float* na = node_attr + (size_t)n * FN;
        #pragma unroll
        for (int k = 0; k < FN; k++) {
            float a = __ldg(na + k);
            float4 w = *reinterpret_cast<const float4*>(sWn + k * HID + c0);
            fma4(acc, a, w);
        }
        const float* ag = g_agg8 + (size_t)n * FE;
        #pragma unroll
        for (int k = 0; k < FE; k++) {
            float a = ag[k];
            float4 w = *reinterpret_cast<const float4*>(sWe + k * HID + c0);
            fma4(acc, a, w);
        }
        relu4(acc);
        *reinterpret_cast<float4*>(g_h + (size_t)n * HID + c0) = acc;
    }
}

// ---------------- tiled 128x128 GEMM: g_hw = X @ W + b ------------------------
// X selected by xsel: 0 = g_h, 2 = g_h2.  64-row tiles, W resident in smem.
__global__ void k_gemm_t(int xsel,
                         const float* __restrict__ W,
                         const float* __restrict__ b) {
    extern __shared__ float sm[];
    float* sW = sm;            // 128*128
    float* sX = sm + 16384;    // 64*128

    const float* X = (xsel == 0) ? g_h : g_h2;
    float* Y = g_hw;

    int tid = threadIdx.x;
    for (int i = tid; i < 4096; i += 256)       // 16384 floats as float4
        reinterpret_cast<float4*>(sW)[i] = reinterpret_cast<const float4*>(W)[i];

    int tr = tid >> 5;     // 0..7  (== warp id)
    int tc = tid & 31;     // 0..31
    float4 bias = __ldg(reinterpret_cast<const float4*>(b) + tc);

    int ntiles = (NN + 63) >> 6;
    for (int t = blockIdx.x; t < ntiles; t += gridDim.x) {
        int n0 = t << 6;
        __syncthreads();
        for (int i = tid; i < 2048; i += 256) {   // 64*128 floats as float4
            int r = i >> 5;
            int gi = n0 + r;
            reinterpret_cast<float4*>(sX)[i] =
                (gi < NN) ? reinterpret_cast<const float4*>(X)[(size_t)gi * 32 + (i & 31)]
                          : make_float4(0.f, 0.f, 0.f, 0.f);
        }
        __syncthreads();

        float4 acc[8];
        #pragma unroll
        for (int i = 0; i < 8; i++) acc[i] = bias;

        #pragma unroll 4
        for (int k = 0; k < 128; k++) {
            float4 wv = reinterpret_cast<float4*>(sW)[k * 32 + tc];
            const float* xc = sX + (tr * 8) * 128 + k;
            #pragma unroll
            for (int i = 0; i < 8; i++) {
                float xv = xc[i * 128];
                fma4(acc[i], xv, wv);
            }
        }
        #pragma unroll
        for (int i = 0; i < 8; i++) {
            int r = n0 + tr * 8 + i;
            if (r < NN)
                reinterpret_cast<float4*>(Y)[(size_t)r * 32 + tc] = acc[i];
        }
    }
}

// ---------------- sparse aggregate: out[n] = relu(sum val * hw[dst]) ----------
__global__ void k_agg(int outsel) {
    float* out = (outsel == 0) ? g_h : g_h2;
    int lane = threadIdx.x & 31;
    int wid  = threadIdx.x >> 5;
    int gw = blockIdx.x * (blockDim.x >> 5) + wid;
    int nwarps = gridDim.x * (blockDim.x >> 5);
    const float4* hw4 = reinterpret_cast<const float4*>(g_hw);

    for (int n = gw; n < NN; n += nwarps) {
        float4 acc = make_float4(0.f, 0.f, 0.f, 0.f);
        int pbeg = g_rp[0][n], pend = g_rp[0][n + 1];
        for (int p = pbeg; p < pend; p++) {
            int d = g_dst_perm[p];
            float v = g_val_perm[p];
            float4 hv = __ldg(&hw4[(size_t)d * 32 + lane]);
            fma4(acc, v, hv);
        }
        relu4(acc);
        *reinterpret_cast<float4*>(out + (size_t)n * HID + lane * 4) = acc;
    }
}

// ---------------- graph boundaries via binary search (batch is sorted) --------
__global__ void k_bounds(const int* __restrict__ batch) {
    int g = blockIdx.x * blockDim.x + threadIdx.x;
    if (g > NG) return;
    int lo = 0, hi = NN;
    while (lo < hi) {
        int mid = (lo + hi) >> 1;
        if (batch[mid] < g) lo = mid + 1; else hi = mid;
    }
    g_rpg[g] = lo;
}

// ---------------- global_add_pool (block per graph, no atomics) ----------------
__global__ void k_pool() {
    int g = blockIdx.x;
    int c = threadIdx.x;
    int s = g_rpg[g], e = g_rpg[g + 1];
    float acc = 0.f;
    for (int n = s; n < e; n++)
        acc += __ldg(g_h2 + (size_t)n * HID + c);
    g_fp[(size_t)g * HID + c] = acc;
}

// ---------------- predictor MLP ------------------------------------------------
__global__ void k_pred(const float* __restrict__ Wp1,
                       const float* __restrict__ bp1,
                       const float* __restrict__ Wp2,
                       const float* __restrict__ bp2,
                       float* __restrict__ out) {
    int lane = threadIdx.x & 31;
    int wid  = threadIdx.x >> 5;
    int gw = blockIdx.x * (blockDim.x >> 5) + wid;
    int nwarps = gridDim.x * (blockDim.x >> 5);
    const float4* W4 = reinterpret_cast<const float4*>(Wp1);

    for (int g = gw; g < NG; g += nwarps) {
        float4 acc = *reinterpret_cast<const float4*>(bp1 + lane * 4);
        const float* xr = g_fp + (size_t)g * HID;
        #pragma unroll 8
        for (int k = 0; k < HID; k++) {
            float a = xr[k];
            float4 w = __ldg(&W4[k * 32 + lane]);
            fma4(acc, a, w);
        }
        relu4(acc);
        float4 wp = *reinterpret_cast<const float4*>(Wp2 + lane * 4);
        float part = acc.x * wp.x + acc.y * wp.y + acc.z * wp.z + acc.w * wp.w;
        #pragma unroll
        for (int off = 16; off > 0; off >>= 1)
            part += __shfl_down_sync(0xFFFFFFFFu, part, off);
        if (lane == 0) out[g] = part + bp2[0];
    }
}

// ---------------- launch ------------------------------------------------------
extern "C" void kernel_launch(void* const* d_in, const int* in_sizes, int n_in,
                              void* d_out, int out_size) {
    const float* node_attr = (const float*)d_in[0];
    const float* edge_attr = (const float*)d_in[1];
    const int*   edge_index = (const int*)d_in[2];   // [2, E]
    const int*   adj_index  = (const int*)d_in[3];   // [2, E]
    const float* adj_value  = (const float*)d_in[4];
    const int*   batch      = (const int*)d_in[5];
    const float* W_node = (const float*)d_in[6];
    const float* W_edge = (const float*)d_in[7];
    const float* b_embed = (const float*)d_in[8];
    const float* W1 = (const float*)d_in[9];
    const float* b1 = (const float*)d_in[10];
    const float* W2 = (const float*)d_in[11];
    const float* b2 = (const float*)d_in[12];
    const float* W3 = (const float*)d_in[13];
    const float* b3 = (const float*)d_in[14];
    const float* Wp1 = (const float*)d_in[15];
    const float* bp1 = (const float*)d_in[16];
    const float* Wp2 = (const float*)d_in[17];
    const float* bp2 = (const float*)d_in[18];
    float* out = (float*)d_out;

    const int* adj_src = adj_index;
    const int* adj_dst = adj_index + NE;
    const int* e_dst   = edge_index + NE;

    const int GEMM_SMEM = (16384 + 8192) * 4;   // 96 KB
    cudaFuncSetAttribute(k_gemm_t, cudaFuncAttributeMaxDynamicSharedMemorySize,
                         GEMM_SMEM);

    // ---- CSR build ----
    k_zero<<<(NN + 511) / 512, 512>>>();
    k_hist<<<2048, 256>>>(adj_src, e_dst);
    k_scan_partial<<<NB_SCAN, 256>>>(0);
    k_scan_partial<<<NB_SCAN, 256>>>(1);
    k_scan_blocks<<<1, 512>>>(0);
    k_scan_blocks<<<1, 512>>>(1);
    k_scan_emit<<<NB_SCAN, 256>>>(0);
    k_scan_emit<<<NB_SCAN, 256>>>(1);
    k_fill<<<2048, 256>>>(adj_src, adj_dst, adj_value, e_dst);

    // ---- embedder (linearity: segsum(E@We) = segsum(E)@We) ----
    k_agg8<<<3125, 256>>>(edge_attr);
    k_embed<<<3125, 256>>>(node_attr, W_node, W_edge, b_embed);

    // ---- 3 GCN layers ----
    k_gemm_t<<<296, 256, GEMM_SMEM>>>(0, W1, b1);   // g_h  -> g_hw
    k_agg   <<<3125, 256>>>(1);                     // g_hw -> g_h2
    k_gemm_t<<<296, 256, GEMM_SMEM>>>(2, W2, b2);   // g_h2 -> g_hw
    k_agg   <<<3125, 256>>>(0);                     // g_hw -> g_h
    k_gemm_t<<<296, 256, GEMM_SMEM>>>(0, W3, b3);   // g_h  -> g_hw
    k_agg   <<<3125, 256>>>(1);                     // g_hw -> g_h2

    // ---- pool + predictor ----
    k_bounds<<<3, 1024>>>(batch);
    k_pool<<<NG, 128>>>();
    k_pred<<<64, 256>>>(Wp1, bp1, Wp2, bp2, out);
}

// round 14
// speedup vs baseline: 1.0060x; 1.0060x over previous
#include <cuda_runtime.h>

#define NN 100000
#define NE 1600000
#define HID 128
#define NG 2048
#define FN 16
#define FE 8
#define NB_SCAN 391   /* ceil(NN/256) */

// ---------------- scratch (static device globals; no allocation) -------------
__device__ float g_h [NN * HID];
__device__ float g_hw[NN * HID];
__device__ float g_h2[NN * HID];
__device__ float g_agg8[NN * FE];

__device__ int g_deg [2][NN];
__device__ int g_rp  [2][NN + 1];
__device__ int g_cur [2][NN];
__device__ int g_bsum[2][NB_SCAN];
__device__ int g_boff[2][NB_SCAN];

__device__ int   g_dst_perm[NE];
__device__ float g_val_perm[NE];
__device__ int   g_eid_perm[NE];

__device__ int   g_rpg[NG + 1];
__device__ float g_fp[NG * HID];

// ---------------- helpers ----------------------------------------------------
__device__ __forceinline__ void fma4(float4& a, float s, const float4& w) {
    a.x += s * w.x; a.y += s * w.y; a.z += s * w.z; a.w += s * w.w;
}
__device__ __forceinline__ void relu4(float4& a) {
    a.x = fmaxf(a.x, 0.f); a.y = fmaxf(a.y, 0.f);
    a.z = fmaxf(a.z, 0.f); a.w = fmaxf(a.w, 0.f);
}

// ---------------- zero degree counters ---------------------------------------
__global__ void k_zero() {
    int i = blockIdx.x * blockDim.x + threadIdx.x;
    if (i < NN) { g_deg[0][i] = 0; g_deg[1][i] = 0; }
}

// ---------------- degree histograms ------------------------------------------
__global__ void k_hist(const int* __restrict__ adj_src,
                       const int* __restrict__ e_dst) {
    int i = blockIdx.x * blockDim.x + threadIdx.x;
    int stride = gridDim.x * blockDim.x;
    for (int e = i; e < NE; e += stride) {
        atomicAdd(&g_deg[0][adj_src[e]], 1);
        atomicAdd(&g_deg[1][e_dst[e]], 1);
    }
}

// ---------------- parallel scan: phase 1 (per-block sums) --------------------
__global__ void k_scan_partial(int which) {
    __shared__ int s[256];
    int b = blockIdx.x;
    int i = b * 256 + threadIdx.x;
    int v = (i < NN) ? g_deg[which][i] : 0;
    s[threadIdx.x] = v;
    __syncthreads();
    for (int off = 128; off > 0; off >>= 1) {
        if (threadIdx.x < off) s[threadIdx.x] += s[threadIdx.x + off];
        __syncthreads();
    }
    if (threadIdx.x == 0) g_bsum[which][b] = s[0];
}

// ---------------- parallel scan: phase 2 (scan of block sums, 1 block) -------
__global__ void k_scan_blocks(int which) {
    __shared__ int s[512];
    int tid = threadIdx.x;
    int v = (tid < NB_SCAN) ? g_bsum[which][tid] : 0;
    s[tid] = v;
    __syncthreads();
    for (int off = 1; off < 512; off <<= 1) {
        int t = (tid >= off) ? s[tid - off] : 0;
        __syncthreads();
        s[tid] += t;
        __syncthreads();
    }
    if (tid < NB_SCAN) g_boff[which][tid] = s[tid] - v;   // exclusive
    if (tid == 511) g_rp[which][NN] = s[511];             // total
}

// ---------------- parallel scan: phase 3 (emit rp/cur) ------------------------
__global__ void k_scan_emit(int which) {
    __shared__ int s[256];
    int b = blockIdx.x;
    int tid = threadIdx.x;
    int i = b * 256 + tid;
    int d = (i < NN) ? g_deg[which][i] : 0;
    s[tid] = d;
    __syncthreads();
    for (int off = 1; off < 256; off <<= 1) {
        int t = (tid >= off) ? s[tid - off] : 0;
        __syncthreads();
        s[tid] += t;
        __syncthreads();
    }
    if (i < NN) {
        int rp = g_boff[which][b] + s[tid] - d;
        g_rp[which][i] = rp;
        g_cur[which][i] = rp;
    }
}

// ---------------- CSR fill (permutation) -------------------------------------
__global__ void k_fill(const int* __restrict__ adj_src,
                       const int* __restrict__ adj_dst,
                       const float* __restrict__ adj_val,
                       const int* __restrict__ e_dst) {
    int i = blockIdx.x * blockDim.x + threadIdx.x;
    int stride = gridDim.x * blockDim.x;
    for (int e = i; e < NE; e += stride) {
        int pos = atomicAdd(&g_cur[0][adj_src[e]], 1);
        g_dst_perm[pos] = adj_dst[e];
        g_val_perm[pos] = adj_val[e];
        int p2 = atomicAdd(&g_cur[1][e_dst[e]], 1);
        g_eid_perm[p2] = e;
    }
}

// ---------------- 8-dim raw edge feature aggregation --------------------------
// g_agg8[n][c] = sum over incoming edges e of edge_attr[e][c]
__global__ void k_agg8(const float* __restrict__ edge_attr) {
    int lane = threadIdx.x & 31;
    int wid  = threadIdx.x >> 5;
    int gw = blockIdx.x * (blockDim.x >> 5) + wid;
    int nwarps = gridDim.x * (blockDim.x >> 5);
    int sub = lane >> 3;     // 0..3 : edge slot
    int col = lane & 7;      // 0..7 : feature

    for (int n = gw; n < NN; n += nwarps) {
        int pbeg = g_rp[1][n], pend = g_rp[1][n + 1];
        float v = 0.f;
        for (int p = pbeg + sub; p < pend; p += 4) {
            int e = g_eid_perm[p];
            v += __ldg(edge_attr + (size_t)e * FE + col);
        }
        v += __shfl_down_sync(0xFFFFFFFFu, v, 16);
        v += __shfl_down_sync(0xFFFFFFFFu, v, 8);
        if (lane < 8) g_agg8[(size_t)n * FE + lane] = v;
    }
}

// ---------------- attr embedder: h = relu([node|agg8] @ [Wn;We] + b) ----------
__global__ void k_embed(const float* __restrict__ node_attr,
                        const float* __restrict__ W_node,
                        const float* __restrict__ W_edge,
                        const float* __restrict__ b_embed) {
    __shared__ float sWn[FN * HID];
    __shared__ float sWe[FE * HID];
    for (int i = threadIdx.x; i < FN * HID; i += blockDim.x) sWn[i] = W_node[i];
    for (int i = threadIdx.x; i < FE * HID; i += blockDim.x) sWe[i] = W_edge[i];
    __syncthreads();

    int lane = threadIdx.x & 31;
    int wid  = threadIdx.x >> 5;
    int gw = blockIdx.x * (blockDim.x >> 5) + wid;
    int nwarps = gridDim.x * (blockDim.x >> 5);
    int c0 = lane * 4;

    for (int n = gw; n < NN; n += nwarps) {
        float4 acc = *reinterpret_cast<const float4*>(b_embed + c0);
        const float* na = node_attr + (size_t)n * FN;
        #pragma unroll
        for (int k = 0; k < FN; k++) {
            float a = __ldg(na + k);
            float4 w = *reinterpret_cast<const float4*>(sWn + k * HID + c0);
            fma4(acc, a, w);
        }
        const float* ag = g_agg8 + (size_t)n * FE;
        #pragma unroll
        for (int k = 0; k < FE; k++) {
            float a = ag[k];
            float4 w = *reinterpret_cast<const float4*>(sWe + k * HID + c0);
            fma4(acc, a, w);
        }
        relu4(acc);
        *reinterpret_cast<float4*>(g_h + (size_t)n * HID + c0) = acc;
    }
}

// ---------------- tiled 128x128 GEMM: g_hw = X @ W + b ------------------------
// X selected by xsel: 0 = g_h, 2 = g_h2.  64-row tiles, W resident in smem.
__global__ void k_gemm_t(int xsel,
                         const float* __restrict__ W,
                         const float* __restrict__ b) {
    extern __shared__ float sm[];
    float* sW = sm;            // 128*128
    float* sX = sm + 16384;    // 64*128

    const float* X = (xsel == 0) ? g_h : g_h2;
    float* Y = g_hw;

    int tid = threadIdx.x;
    for (int i = tid; i < 4096; i += 256)       // 16384 floats as float4
        reinterpret_cast<float4*>(sW)[i] = reinterpret_cast<const float4*>(W)[i];

    int tr = tid >> 5;     // 0..7  (== warp id)
    int tc = tid & 31;     // 0..31
    float4 bias = __ldg(reinterpret_cast<const float4*>(b) + tc);

    int ntiles = (NN + 63) >> 6;
    for (int t = blockIdx.x; t < ntiles; t += gridDim.x) {
        int n0 = t << 6;
        __syncthreads();
        for (int i = tid; i < 2048; i += 256) {   // 64*128 floats as float4
            int r = i >> 5;
            int gi = n0 + r;
            reinterpret_cast<float4*>(sX)[i] =
                (gi < NN) ? reinterpret_cast<const float4*>(X)[(size_t)gi * 32 + (i & 31)]
                          : make_float4(0.f, 0.f, 0.f, 0.f);
        }
        __syncthreads();

        float4 acc[8];
        #pragma unroll
        for (int i = 0; i < 8; i++) acc[i] = bias;

        #pragma unroll 4
        for (int k = 0; k < 128; k++) {
            float4 wv = reinterpret_cast<float4*>(sW)[k * 32 + tc];
            const float* xc = sX + (tr * 8) * 128 + k;
            #pragma unroll
            for (int i = 0; i < 8; i++) {
                float xv = xc[i * 128];
                fma4(acc[i], xv, wv);
            }
        }
        #pragma unroll
        for (int i = 0; i < 8; i++) {
            int r = n0 + tr * 8 + i;
            if (r < NN)
                reinterpret_cast<float4*>(Y)[(size_t)r * 32 + tc] = acc[i];
        }
    }
}

// ---------------- sparse aggregate: out[n] = relu(sum val * hw[dst]) ----------
__global__ void k_agg(int outsel) {
    float* out = (outsel == 0) ? g_h : g_h2;
    int lane = threadIdx.x & 31;
    int wid  = threadIdx.x >> 5;
    int gw = blockIdx.x * (blockDim.x >> 5) + wid;
    int nwarps = gridDim.x * (blockDim.x >> 5);
    const float4* hw4 = reinterpret_cast<const float4*>(g_hw);

    for (int n = gw; n < NN; n += nwarps) {
        float4 acc = make_float4(0.f, 0.f, 0.f, 0.f);
        int pbeg = g_rp[0][n], pend = g_rp[0][n + 1];
        for (int p = pbeg; p < pend; p++) {
            int d = g_dst_perm[p];
            float v = g_val_perm[p];
            float4 hv = __ldg(&hw4[(size_t)d * 32 + lane]);
            fma4(acc, v, hv);
        }
        relu4(acc);
        *reinterpret_cast<float4*>(out + (size_t)n * HID + lane * 4) = acc;
    }
}

// ---------------- graph boundaries via binary search (batch is sorted) --------
__global__ void k_bounds(const int* __restrict__ batch) {
    int g = blockIdx.x * blockDim.x + threadIdx.x;
    if (g > NG) return;
    int lo = 0, hi = NN;
    while (lo < hi) {
        int mid = (lo + hi) >> 1;
        if (batch[mid] < g) lo = mid + 1; else hi = mid;
    }
    g_rpg[g] = lo;
}

// ---------------- global_add_pool (block per graph, no atomics) ----------------
__global__ void k_pool() {
    int g = blockIdx.x;
    int c = threadIdx.x;
    int s = g_rpg[g], e = g_rpg[g + 1];
    float acc = 0.f;
    for (int n = s; n < e; n++)
        acc += __ldg(g_h2 + (size_t)n * HID + c);
    g_fp[(size_t)g * HID + c] = acc;
}

// ---------------- predictor MLP ------------------------------------------------
__global__ void k_pred(const float* __restrict__ Wp1,
                       const float* __restrict__ bp1,
                       const float* __restrict__ Wp2,
                       const float* __restrict__ bp2,
                       float* __restrict__ out) {
    int lane = threadIdx.x & 31;
    int wid  = threadIdx.x >> 5;
    int gw = blockIdx.x * (blockDim.x >> 5) + wid;
    int nwarps = gridDim.x * (blockDim.x >> 5);
    const float4* W4 = reinterpret_cast<const float4*>(Wp1);

    for (int g = gw; g < NG; g += nwarps) {
        float4 acc = *reinterpret_cast<const float4*>(bp1 + lane * 4);
        const float* xr = g_fp + (size_t)g * HID;
        #pragma unroll 8
        for (int k = 0; k < HID; k++) {
            float a = xr[k];
            float4 w = __ldg(&W4[k * 32 + lane]);
            fma4(acc, a, w);
        }
        relu4(acc);
        float4 wp = *reinterpret_cast<const float4*>(Wp2 + lane * 4);
        float part = acc.x * wp.x + acc.y * wp.y + acc.z * wp.z + acc.w * wp.w;
        #pragma unroll
        for (int off = 16; off > 0; off >>= 1)
            part += __shfl_down_sync(0xFFFFFFFFu, part, off);
        if (lane == 0) out[g] = part + bp2[0];
    }
}

// ---------------- launch ------------------------------------------------------
extern "C" void kernel_launch(void* const* d_in, const int* in_sizes, int n_in,
                              void* d_out, int out_size) {
    const float* node_attr = (const float*)d_in[0];
    const float* edge_attr = (const float*)d_in[1];
    const int*   edge_index = (const int*)d_in[2];   // [2, E]
    const int*   adj_index  = (const int*)d_in[3];   // [2, E]
    const float* adj_value  = (const float*)d_in[4];
    const int*   batch      = (const int*)d_in[5];
    const float* W_node = (const float*)d_in[6];
    const float* W_edge = (const float*)d_in[7];
    const float* b_embed = (const float*)d_in[8];
    const float* W1 = (const float*)d_in[9];
    const float* b1 = (const float*)d_in[10];
    const float* W2 = (const float*)d_in[11];
    const float* b2 = (const float*)d_in[12];
    const float* W3 = (const float*)d_in[13];
    const float* b3 = (const float*)d_in[14];
    const float* Wp1 = (const float*)d_in[15];
    const float* bp1 = (const float*)d_in[16];
    const float* Wp2 = (const float*)d_in[17];
    const float* bp2 = (const float*)d_in[18];
    float* out = (float*)d_out;

    const int* adj_src = adj_index;
    const int* adj_dst = adj_index + NE;
    const int* e_dst   = edge_index + NE;

    const int GEMM_SMEM = (16384 + 8192) * 4;   // 96 KB
    cudaFuncSetAttribute(k_gemm_t, cudaFuncAttributeMaxDynamicSharedMemorySize,
                         GEMM_SMEM);

    // ---- CSR build ----
    k_zero<<<(NN + 511) / 512, 512>>>();
    k_hist<<<2048, 256>>>(adj_src, e_dst);
    k_scan_partial<<<NB_SCAN, 256>>>(0);
    k_scan_partial<<<NB_SCAN, 256>>>(1);
    k_scan_blocks<<<1, 512>>>(0);
    k_scan_blocks<<<1, 512>>>(1);
    k_scan_emit<<<NB_SCAN, 256>>>(0);
    k_scan_emit<<<NB_SCAN, 256>>>(1);
    k_fill<<<2048, 256>>>(adj_src, adj_dst, adj_value, e_dst);

    // ---- embedder (linearity: segsum(E@We) = segsum(E)@We) ----
    k_agg8<<<3125, 256>>>(edge_attr);
    k_embed<<<3125, 256>>>(node_attr, W_node, W_edge, b_embed);

    // ---- 3 GCN layers ----
    k_gemm_t<<<296, 256, GEMM_SMEM>>>(0, W1, b1);   // g_h  -> g_hw
    k_agg   <<<3125, 256>>>(1);                     // g_hw -> g_h2
    k_gemm_t<<<296, 256, GEMM_SMEM>>>(2, W2, b2);   // g_h2 -> g_hw
    k_agg   <<<3125, 256>>>(0);                     // g_hw -> g_h
    k_gemm_t<<<296, 256, GEMM_SMEM>>>(0, W3, b3);   // g_h  -> g_hw
    k_agg   <<<3125, 256>>>(1);                     // g_hw -> g_h2

    // ---- pool + predictor ----
    k_bounds<<<3, 1024>>>(batch);
    k_pool<<<NG, 128>>>();
    k_pred<<<64, 256>>>(Wp1, bp1, Wp2, bp2, out);
}